// round 16
// baseline (speedup 1.0000x reference)
#include <cuda_runtime.h>
#include <cstdint>

#define NB 16
#define NC 80
#define NN 21824
#define KC 256
#define CAP2 2048      // per-(b,c) global candidate cap (E[M]~469 @ T0=0.8)
#define MPC 100
#define MD 100
#define CONF 0.05f
#define T0 0.8f        // pre-filter threshold; M>=256 at 10 sigma; exact fallback else
#define HB 768         // histogram bins (bits>>16 granularity)
#define HOFF 0x3D00u   // bin = (bits>>16) - HOFF; 0.05->0x4C, 1.0->0x280, <768
#define RPB 96         // anchors per filter block

// Scratch (device globals: no runtime allocation allowed; BSS-zero at start)
__device__ unsigned g_cnt[NB * NC * 32];                       // 128B-strided counters
__device__ unsigned g_arrive[NB * 32];                         // per-batch arrival counters
__device__ unsigned long long g_cand[(size_t)NB * NC * CAP2];  // (bits<<32)|~n per (b,c)
__device__ float g_cls_scores[NB * NC * MPC];
__device__ float g_cls_boxes[NB * NC * MPC * 4];

// ---------------------------------------------------------------------------
// K0 (tile version, count-then-emit, measured 33.6us @ T0=0.8)
// ---------------------------------------------------------------------------
__global__ __launch_bounds__(256) void k_filter(const float* __restrict__ clf,
                                                const float* __restrict__ ctr) {
    __shared__ float tile[RPB * NC];   // 30720 B
    __shared__ float ctr_s[RPB];
    int b = blockIdx.y;
    int n0 = blockIdx.x * RPB;
    int tid = threadIdx.x;
    int rows = NN - n0; if (rows > RPB) rows = RPB;

    const float4* src = reinterpret_cast<const float4*>(clf + ((size_t)b * NN + n0) * NC);
    int nf4 = rows * (NC / 4);
    for (int i = tid; i < nf4; i += 256) reinterpret_cast<float4*>(tile)[i] = src[i];
    for (int i = tid; i < rows; i += 256) ctr_s[i] = ctr[(size_t)b * NN + n0 + i];
    __syncthreads();

    if (tid < 240) {
        int c = tid % 80;
        int r0 = (tid / 80) * 32;
        int r1 = r0 + 32; if (r1 > rows) r1 = rows;
        int cnt = 0;
        for (int r = r0; r < r1; r++) {
            float s = tile[r * NC + c] * ctr_s[r];
            if (s > T0) cnt++;
        }
        if (cnt) {
            int bc = b * NC + c;
            unsigned base = atomicAdd(&g_cnt[bc * 32], (unsigned)cnt);
            unsigned long long* dst = g_cand + (size_t)bc * CAP2;
            for (int r = r0; r < r1; r++) {
                float s = tile[r * NC + c] * ctr_s[r];
                if (s > T0) {
                    if (base < CAP2) {
                        unsigned n = (unsigned)(n0 + r);
                        dst[base] = ((unsigned long long)__float_as_uint(s) << 32)
                                    | (0xFFFFFFFFu - n);
                    }
                    base++;
                }
            }
        }
    }
}

// ---------------------------------------------------------------------------
// Shared bitonic sort (descending) over P (power of 2) u64 keys, 256 threads
// ---------------------------------------------------------------------------
__device__ __forceinline__ void bitonic_desc(unsigned long long* cand, int P, int tid) {
    for (int kk = 2; kk <= P; kk <<= 1) {
        for (int jj = kk >> 1; jj > 0; jj >>= 1) {
            for (int i = tid; i < P; i += 256) {
                int ixj = i ^ jj;
                if (ixj > i) {
                    unsigned long long a = cand[i], bb = cand[ixj];
                    bool sw = ((i & kk) == 0) ? (a < bb) : (a > bb);
                    if (sw) { cand[i] = bb; cand[ixj] = a; }
                }
            }
            __syncthreads();
        }
    }
}

// ---------------------------------------------------------------------------
// K1: per (b,c): top-128 fast path, exact top-256 fallback; the last block of
// each batch runs the final per-batch top-100 in its tail (fused k_final).
// ---------------------------------------------------------------------------
__global__ void __launch_bounds__(256, 8) k_nms(const float* __restrict__ regs,
                                                const float* __restrict__ clf,
                                                const float* __restrict__ ctr,
                                                float* __restrict__ out) {
    __shared__ unsigned hist[HB];
    __shared__ unsigned long long cand[2048];   // sort buf; [1024..] aliased as srow (fallback)
    __shared__ float4 bb[256];
    __shared__ unsigned scol[512];              // fast-path suppression columns [w*128+j]
    __shared__ unsigned keepw[8], keepr[8], sh_wt[8];
    __shared__ unsigned sh_Ta, sh_Tb, sh_cnt, sh_tot, sh_kept, sh_last;

    int bc = blockIdx.x;
    int b = bc / NC;
    int c = bc % NC;
    int tid = threadIdx.x;
    int lane = tid & 31;
    int wrp = tid >> 5;

    int M = (int)g_cnt[bc * 32];
    const unsigned long long* src = g_cand + (size_t)bc * CAP2;
    bool srcok = (M >= KC && M <= CAP2);

    for (int i = tid; i < HB; i += 256) hist[i] = 0;
    if (tid == 0) { sh_cnt = 0; sh_tot = 0; sh_kept = 0; sh_last = 0; }
    __syncthreads();
    if (tid == 0) g_cnt[bc * 32] = 0;      // self-reset for next graph replay

    // ---- histogram ----
    if (srcok) {
        for (int i = tid; i < M; i += 256)
            atomicAdd(&hist[(unsigned)(src[i] >> 48) - HOFF], 1u);
    } else {
        const float* cb_ = clf + (size_t)b * NN * NC + c;
        const float* tb = ctr + (size_t)b * NN;
        unsigned loc = 0;
        for (int n = tid; n < NN; n += 256) {
            float s = cb_[(size_t)n * NC] * tb[n];
            if (s > CONF) { atomicAdd(&hist[(__float_as_uint(s) >> 16) - HOFF], 1u); loc++; }
        }
        atomicAdd(&sh_tot, loc);
    }
    __syncthreads();
    int tot = srcok ? M : (int)sh_tot;

    // ---- suffix sums over 256 coarse bins (3 fine each): shfl + 1 barrier ----
    unsigned csum = hist[tid * 3] + hist[tid * 3 + 1] + hist[tid * 3 + 2];
    unsigned sfx = csum;
    #pragma unroll
    for (int off = 1; off < 32; off <<= 1) {
        unsigned t = __shfl_down_sync(0xFFFFFFFFu, sfx, off);
        if (lane + off < 32) sfx += t;
    }
    if (lane == 0) sh_wt[wrp] = sfx;
    __syncthreads();
    {
        unsigned hi = 0;
        #pragma unroll
        for (int w2 = 0; w2 < 8; w2++) if (w2 > wrp) hi += sh_wt[w2];
        unsigned St = sfx + hi;
        unsigned Sn = St - csum;
        int tgtA = tot < 128 ? tot : 128;
        int tgtB = tot < KC ? tot : KC;
        if (tgtA == 0) { if (tid == 0) { sh_Ta = HB; sh_Tb = HB; } }
        else {
            if (St >= (unsigned)tgtA && Sn < (unsigned)tgtA) {
                unsigned cum = Sn; int bin = tid * 3 + 2;
                for (; bin >= tid * 3; bin--) { cum += hist[bin]; if (cum >= (unsigned)tgtA) break; }
                sh_Ta = (unsigned)(bin < tid * 3 ? tid * 3 : bin);
            }
            if (St >= (unsigned)tgtB && Sn < (unsigned)tgtB) {
                unsigned cum = Sn; int bin = tid * 3 + 2;
                for (; bin >= tid * 3; bin--) { cum += hist[bin]; if (cum >= (unsigned)tgtB) break; }
                sh_Tb = (unsigned)(bin < tid * 3 ? tid * 3 : bin);
            }
        }
    }
    __syncthreads();

    float y1 = 0.f, x1 = 0.f, y2 = 0.f, x2 = 0.f, score = 0.f;
    bool need256 = !srcok;
    int rt = bc & 255;

    // =================== FAST PATH: top-128 ===================
    if (!need256) {
        unsigned Ta = sh_Ta;
        for (int i = tid; i < M; i += 256) {
            unsigned long long key = src[i];
            if ((unsigned)(key >> 48) - HOFF >= Ta) {
                unsigned p = atomicAdd(&sh_cnt, 1u);
                if (p < 256) cand[p] = key;
            }
        }
        __syncthreads();
        int C = (int)sh_cnt;
        if (C > 256) need256 = true;
        else {
            for (int i = C + tid; i < 256; i += 256) cand[i] = 0ULL;
            __syncthreads();

            // register bitonic sort of 256 (desc): shfl intra-warp, smem jj>=32
            unsigned long long v = cand[tid];
            #pragma unroll
            for (int kk = 2; kk <= 32; kk <<= 1) {
                #pragma unroll
                for (int jj = kk >> 1; jj > 0; jj >>= 1) {
                    unsigned long long pv = __shfl_xor_sync(0xFFFFFFFFu, v, jj);
                    bool keep_max = (((tid & jj) == 0) == ((tid & kk) == 0));
                    if (keep_max ? (pv > v) : (pv < v)) v = pv;
                }
            }
            #pragma unroll
            for (int kk = 64; kk <= 256; kk <<= 1) {
                for (int jj = kk >> 1; jj >= 32; jj >>= 1) {
                    __syncthreads();
                    cand[tid] = v;
                    __syncthreads();
                    unsigned long long pv = cand[tid ^ jj];
                    bool keep_max = (((tid & jj) == 0) == ((tid & kk) == 0));
                    if (keep_max ? (pv > v) : (pv < v)) v = pv;
                }
                #pragma unroll
                for (int jj = 16; jj > 0; jj >>= 1) {
                    unsigned long long pv = __shfl_xor_sync(0xFFFFFFFFu, v, jj);
                    bool keep_max = (((tid & jj) == 0) == ((tid & kk) == 0));
                    if (keep_max ? (pv > v) : (pv < v)) v = pv;
                }
            }

            unsigned long long key = v;
            unsigned bits = (unsigned)(key >> 32);
            score = __uint_as_float(bits);
            unsigned n = 0xFFFFFFFFu - (unsigned)(key & 0xFFFFFFFFu);
            bool validk = (key != 0ULL);
            y1 = x1 = y2 = x2 = 0.f;
            if (validk) {
                int l, base;
                if (n < 16384u)      { l = 0; base = 0; }
                else if (n < 20480u) { l = 1; base = 16384; }
                else if (n < 21504u) { l = 2; base = 20480; }
                else if (n < 21760u) { l = 3; base = 21504; }
                else                 { l = 4; base = 21760; }
                int local = (int)n - base;
                int shift = 7 - l;
                float gx = (float)(local >> shift);
                float gy = (float)(local & ((1 << shift) - 1));
                float sF = (float)(8 << l);
                const float4 r = *reinterpret_cast<const float4*>(regs + ((size_t)b * NN + n) * 4);
                y1 = (gy - r.z) * sF; x1 = (gx - r.x) * sF;
                y2 = (gy + r.w) * sF; x2 = (gx + r.y) * sF;
            }
            if (!validk) score = 0.f;
            bb[tid] = make_float4(y1, x1, y2, x2);
            int keepf = (validk && score > CONF) ? 1 : 0;
            unsigned bal0 = __ballot_sync(0xFFFFFFFFu, keepf);
            if (lane == 0) keepw[wrp] = bal0;
            __syncthreads();

            // column-major suppression (ballot-free)
            {
                int j = tid & 127;
                bool hihalf = tid >= 128;
                int i0 = hihalf ? (j >> 1) : 0;
                int i1 = hihalf ? j : (j >> 1);
                float4 cbox = bb[j];
                float ca = (cbox.z - cbox.x) * (cbox.w - cbox.y);
                unsigned cw0 = 0, cw1 = 0, cw2 = 0, cw3 = 0;
                #pragma unroll
                for (int w = 0; w < 4; w++) {
                    int s0 = i0 > w * 32 ? i0 : w * 32;
                    int e0 = i1 < w * 32 + 32 ? i1 : w * 32 + 32;
                    unsigned acc = 0;
                    for (int i = s0; i < e0; i++) {
                        float4 o = bb[i];
                        float ai = (o.z - o.x) * (o.w - o.y);
                        float ih = fminf(o.z, cbox.z) - fmaxf(o.x, cbox.x); ih = fmaxf(ih, 0.0f);
                        float iw = fminf(o.w, cbox.w) - fmaxf(o.y, cbox.y); iw = fmaxf(iw, 0.0f);
                        float inter = ih * iw;
                        float uni = ai + ca - inter; uni = fmaxf(uni, 1e-8f);
                        if (inter > 0.5f * uni) acc |= 1u << (i - w * 32);
                    }
                    if (w == 0) cw0 = acc; else if (w == 1) cw1 = acc;
                    else if (w == 2) cw2 = acc; else cw3 = acc;
                }
                if (!hihalf) {
                    scol[j] = cw0; scol[128 + j] = cw1;
                    scol[256 + j] = cw2; scol[384 + j] = cw3;
                }
                __syncthreads();
                if (hihalf) {
                    scol[j] |= cw0; scol[128 + j] |= cw1;
                    scol[256 + j] |= cw2; scol[384 + j] |= cw3;
                }
            }
            __syncthreads();

            if (tid == rt) {
                unsigned k0 = keepw[0], k1 = keepw[1], k2 = keepw[2], k3 = keepw[3];
                #pragma unroll 4
                for (int j = 0; j < 128; j++) {
                    unsigned sup = (scol[j] & k0) | (scol[128 + j] & k1)
                                 | (scol[256 + j] & k2) | (scol[384 + j] & k3);
                    if (sup) {
                        unsigned m = ~(1u << (j & 31));
                        if (j < 32) k0 &= m; else if (j < 64) k1 &= m;
                        else if (j < 96) k2 &= m; else k3 &= m;
                    }
                }
                keepr[0] = k0; keepr[1] = k1; keepr[2] = k2; keepr[3] = k3;
                keepr[4] = 0; keepr[5] = 0; keepr[6] = 0; keepr[7] = 0;
                sh_kept = (unsigned)(__popc(k0) + __popc(k1) + __popc(k2) + __popc(k3));
            }
            __syncthreads();
            if ((int)sh_kept < MPC) need256 = true;
        }
    }

    // =================== FALLBACK: exact top-256 ===================
    if (need256) {
        if (tid == 0) sh_cnt = 0;
        __syncthreads();
        unsigned Tb = sh_Tb;
        if (srcok) {
            for (int i = tid; i < M; i += 256) {
                unsigned long long key = src[i];
                if ((unsigned)(key >> 48) - HOFF >= Tb) {
                    unsigned p = atomicAdd(&sh_cnt, 1u);
                    if (p < 1024) cand[p] = key;
                }
            }
        } else {
            const float* cb_ = clf + (size_t)b * NN * NC + c;
            const float* tb = ctr + (size_t)b * NN;
            for (int n = tid; n < NN; n += 256) {
                float s = cb_[(size_t)n * NC] * tb[n];
                if (s > CONF) {
                    unsigned bits = __float_as_uint(s);
                    if ((bits >> 16) - HOFF >= Tb) {
                        unsigned p = atomicAdd(&sh_cnt, 1u);
                        if (p < 1024) cand[p] = ((unsigned long long)bits << 32)
                                                | (0xFFFFFFFFu - (unsigned)n);
                    }
                }
            }
        }
        __syncthreads();
        int C = (int)sh_cnt; if (C > 1024) C = 1024;
        int P = (C <= 512) ? 512 : 1024;
        for (int i = C + tid; i < P; i += 256) cand[i] = 0ULL;
        __syncthreads();
        bitonic_desc(cand, P, tid);

        unsigned long long key = cand[tid];
        unsigned bits = (unsigned)(key >> 32);
        score = __uint_as_float(bits);
        unsigned n = 0xFFFFFFFFu - (unsigned)(key & 0xFFFFFFFFu);
        bool validk = (key != 0ULL);
        y1 = x1 = y2 = x2 = 0.f;
        if (validk) {
            int l, base;
            if (n < 16384u)      { l = 0; base = 0; }
            else if (n < 20480u) { l = 1; base = 16384; }
            else if (n < 21504u) { l = 2; base = 20480; }
            else if (n < 21760u) { l = 3; base = 21504; }
            else                 { l = 4; base = 21760; }
            int local = (int)n - base;
            int shift = 7 - l;
            float gx = (float)(local >> shift);
            float gy = (float)(local & ((1 << shift) - 1));
            float sF = (float)(8 << l);
            const float4 r = *reinterpret_cast<const float4*>(regs + ((size_t)b * NN + n) * 4);
            y1 = (gy - r.z) * sF; x1 = (gx - r.x) * sF;
            y2 = (gy + r.w) * sF; x2 = (gx + r.y) * sF;
        }
        if (!validk) score = 0.f;
        bb[tid] = make_float4(y1, x1, y2, x2);
        float aj = (y2 - y1) * (x2 - x1);
        int keepf = (validk && score > CONF) ? 1 : 0;
        unsigned bal0 = __ballot_sync(0xFFFFFFFFu, keepf);
        if (lane == 0) keepw[wrp] = bal0;
        __syncthreads();

        // srow aliases cand[1024..] (cand dead after decode); zero then fill
        unsigned* srow = reinterpret_cast<unsigned*>(cand + 1024);
        for (int i = tid; i < 2048; i += 256) srow[i] = 0;
        __syncthreads();
        {
            int lim = 32 * wrp + 31;
            for (int i = 0; i < lim; i++) {
                float4 o = bb[i];
                float ai = (o.z - o.x) * (o.w - o.y);
                float ih = fminf(o.z, y2) - fmaxf(o.x, y1); ih = fmaxf(ih, 0.0f);
                float iw = fminf(o.w, x2) - fmaxf(o.y, x1); iw = fmaxf(iw, 0.0f);
                float inter = ih * iw;
                float uni = ai + aj - inter; uni = fmaxf(uni, 1e-8f);
                bool pred = (tid > i) && (inter > 0.5f * uni);
                unsigned bl = __ballot_sync(0xFFFFFFFFu, pred);
                if ((tid & 31) == 0) srow[i * 8 + wrp] = bl;
            }
        }
        __syncthreads();

        if (tid == rt) {
            unsigned kw[8];
            #pragma unroll
            for (int w = 0; w < 8; w++) kw[w] = keepw[w];
            #pragma unroll 4
            for (int i = 0; i < 256; i++) {
                if ((kw[i >> 5] >> (i & 31)) & 1u) {
                    const uint4 s0 = *reinterpret_cast<const uint4*>(&srow[i * 8]);
                    const uint4 s1 = *reinterpret_cast<const uint4*>(&srow[i * 8 + 4]);
                    kw[0] &= ~s0.x; kw[1] &= ~s0.y; kw[2] &= ~s0.z; kw[3] &= ~s0.w;
                    kw[4] &= ~s1.x; kw[5] &= ~s1.y; kw[6] &= ~s1.z; kw[7] &= ~s1.w;
                }
            }
            #pragma unroll
            for (int w = 0; w < 8; w++) keepr[w] = kw[w];
        }
        __syncthreads();
    }

    // ---- stable partition via ballot scan (1 barrier) ----
    int keep_j = (keepr[wrp] >> lane) & 1;
    unsigned balk = __ballot_sync(0xFFFFFFFFu, keep_j);
    unsigned pre = __popc(balk & (0xFFFFFFFFu >> (31 - lane)));
    if (lane == 0) sh_wt[wrp] = __popc(balk);
    __syncthreads();
    unsigned base2 = 0, KT = 0;
    #pragma unroll
    for (int w2 = 0; w2 < 8; w2++) {
        unsigned t = sh_wt[w2];
        KT += t;
        if (w2 < wrp) base2 += t;
    }
    int incl = (int)(base2 + pre);
    int slot = keep_j ? (incl - 1) : ((int)KT + tid - incl);
    if (slot < MPC) {
        size_t o = (size_t)bc * MPC + slot;
        g_cls_scores[o] = keep_j ? score : 0.0f;
        float* ob = g_cls_boxes + o * 4;
        ob[0] = y1; ob[1] = x1; ob[2] = y2; ob[3] = x2;
    }

    // ======== fused k_final: last block of batch b does per-batch top-100 ======
    __threadfence();
    __syncthreads();
    if (tid == 0) {
        unsigned old = atomicAdd(&g_arrive[b * 32], 1u);
        if (old == NC - 1) {
            g_arrive[b * 32] = 0;          // reset for next graph replay
            __threadfence();               // acquire all 80 blocks' stores
            sh_last = 1;
        }
    }
    __syncthreads();
    if (!sh_last) return;

    // --- final top-100 of 8000 for batch b (reuses hist, cand, sh_wt) ---
    const int F = NC * MPC;  // 8000
    const float* s = g_cls_scores + (size_t)b * F;

    for (int i = tid; i < HB; i += 256) hist[i] = 0;
    if (tid == 0) { sh_cnt = 0; sh_Ta = 0; sh_tot = 0; }  // sh_Ta=T, sh_tot=mode
    __syncthreads();
    for (int f = tid; f < F; f += 256) {
        unsigned bits = __float_as_uint(s[f]);
        if (bits) atomicAdd(&hist[(bits >> 16) - HOFF], 1u);
    }
    __syncthreads();

    {
        unsigned csum2 = hist[tid * 3] + hist[tid * 3 + 1] + hist[tid * 3 + 2];
        unsigned sfx2 = csum2;
        #pragma unroll
        for (int off = 1; off < 32; off <<= 1) {
            unsigned t = __shfl_down_sync(0xFFFFFFFFu, sfx2, off);
            if (lane + off < 32) sfx2 += t;
        }
        if (lane == 0) sh_wt[wrp] = sfx2;
        __syncthreads();
        unsigned hi = 0, tot2 = 0;
        #pragma unroll
        for (int w2 = 0; w2 < 8; w2++) {
            unsigned t = sh_wt[w2];
            tot2 += t;
            if (w2 > wrp) hi += t;
        }
        unsigned St = sfx2 + hi, Sn = St - csum2;
        if (tot2 >= MD) {
            if (St >= (unsigned)MD && Sn < (unsigned)MD) {
                unsigned cum = Sn; int bin = tid * 3 + 2;
                for (; bin >= tid * 3; bin--) { cum += hist[bin]; if (cum >= (unsigned)MD) break; }
                sh_Ta = (unsigned)(bin < tid * 3 ? tid * 3 : bin);
                sh_tot = 0;
            }
        } else if (tid == 0) { sh_Ta = 0; sh_tot = 1; }
    }
    __syncthreads();
    unsigned T = sh_Ta; int mode = (int)sh_tot;

    for (int f = tid; f < F; f += 256) {
        unsigned bits = __float_as_uint(s[f]);
        if (!bits) continue;
        unsigned k = (bits >> 16) - HOFF;
        if (mode == 1 || k >= T) {
            unsigned p = atomicAdd(&sh_cnt, 1u);
            if (p < 2048) cand[p] = ((unsigned long long)bits << 32) | (unsigned)(0xFFFFFFFFu - (unsigned)f);
        }
    }
    __syncthreads();
    int Mf = (int)sh_cnt; if (Mf > 2048) Mf = 2048;
    int P = 256; while (P < Mf) P <<= 1;
    for (int i = Mf + tid; i < P; i += 256) cand[i] = 0ULL;
    __syncthreads();

    bitonic_desc(cand, P, tid);

    float* outB = out;                       // [NB][MD][4]
    float* outL = out + (size_t)NB * MD * 4; // [NB][MD]
    float* outS = out + (size_t)NB * MD * 5; // [NB][MD]

    int lim = (mode == 0) ? MD : (Mf < MD ? Mf : MD);
    if (tid < lim) {
        unsigned long long key = cand[tid];
        unsigned bits = (unsigned)(key >> 32);
        float sv = __uint_as_float(bits);
        unsigned f = 0xFFFFFFFFu - (unsigned)(key & 0xFFFFFFFFu);
        int cls = (int)(f / MPC);
        float mul = (sv > 0.0f) ? 1.0f : 0.0f;
        const float* bx = g_cls_boxes + ((size_t)b * F + f) * 4;
        float* ob = outB + ((size_t)b * MD + tid) * 4;
        ob[0] = bx[0] * mul; ob[1] = bx[1] * mul; ob[2] = bx[2] * mul; ob[3] = bx[3] * mul;
        outL[b * MD + tid] = (float)cls;
        outS[b * MD + tid] = sv;
    }
    if (mode == 1 && tid == 0) {
        int slot2 = lim;
        for (int f = 0; f < F && slot2 < MD; f++) {
            if (__float_as_uint(s[f]) == 0u) {
                float* ob = outB + ((size_t)b * MD + slot2) * 4;
                ob[0] = ob[1] = ob[2] = ob[3] = 0.0f;
                outL[b * MD + slot2] = (float)(f / MPC);
                outS[b * MD + slot2] = 0.0f;
                slot2++;
            }
        }
    }
}

// ---------------------------------------------------------------------------
extern "C" void kernel_launch(void* const* d_in, const int* in_sizes, int n_in,
                              void* d_out, int out_size) {
    const float* regs = nullptr;
    const float* ctrs = nullptr;
    const float* clfs = nullptr;
    for (int i = 0; i < n_in; i++) {
        if (in_sizes[i] == NB * NN * 4)        regs = (const float*)d_in[i];
        else if (in_sizes[i] == NB * NN)       ctrs = (const float*)d_in[i];
        else if (in_sizes[i] == NB * NN * NC)  clfs = (const float*)d_in[i];
    }
    float* out = (float*)d_out;

    dim3 fgrid((NN + RPB - 1) / RPB, NB);    // 228 x 16
    k_filter<<<fgrid, 256>>>(clfs, ctrs);
    k_nms<<<NB * NC, 256>>>(regs, clfs, ctrs, out);
}

// round 17
// speedup vs baseline: 1.1032x; 1.1032x over previous
#include <cuda_runtime.h>
#include <cstdint>

#define NB 16
#define NC 80
#define NN 21824
#define KC 256
#define CAP2 2048      // per-(b,c) global candidate cap (E[M]~469 @ T0=0.8)
#define MPC 100
#define MD 100
#define CONF 0.05f
#define T0 0.8f        // pre-filter threshold; M>=256 at 10 sigma; exact fallback else
#define HB 768         // histogram bins (bits>>16 granularity)
#define HOFF 0x3D00u   // bin = (bits>>16) - HOFF; 0.05->0x4C, 1.0->0x280, <768
#define RPB 96         // anchors per filter block

// Scratch (device globals: no runtime allocation allowed; BSS-zero at start)
__device__ unsigned g_cnt[NB * NC * 32];                       // 128B-strided counters
__device__ unsigned long long g_cand[(size_t)NB * NC * CAP2];  // (bits<<32)|~n per (b,c)
__device__ float g_cls_scores[NB * NC * MPC];
__device__ float g_cls_boxes[NB * NC * MPC * 4];

// ---------------------------------------------------------------------------
// K0 (tile version, count-then-emit, measured 33.6us @ T0=0.8)
// ---------------------------------------------------------------------------
__global__ __launch_bounds__(256) void k_filter(const float* __restrict__ clf,
                                                const float* __restrict__ ctr) {
    __shared__ float tile[RPB * NC];   // 30720 B
    __shared__ float ctr_s[RPB];
    int b = blockIdx.y;
    int n0 = blockIdx.x * RPB;
    int tid = threadIdx.x;
    int rows = NN - n0; if (rows > RPB) rows = RPB;

    const float4* src = reinterpret_cast<const float4*>(clf + ((size_t)b * NN + n0) * NC);
    int nf4 = rows * (NC / 4);
    for (int i = tid; i < nf4; i += 256) reinterpret_cast<float4*>(tile)[i] = src[i];
    for (int i = tid; i < rows; i += 256) ctr_s[i] = ctr[(size_t)b * NN + n0 + i];
    __syncthreads();

    if (tid < 240) {
        int c = tid % 80;
        int r0 = (tid / 80) * 32;
        int r1 = r0 + 32; if (r1 > rows) r1 = rows;
        int cnt = 0;
        for (int r = r0; r < r1; r++) {
            float s = tile[r * NC + c] * ctr_s[r];
            if (s > T0) cnt++;
        }
        if (cnt) {
            int bc = b * NC + c;
            unsigned base = atomicAdd(&g_cnt[bc * 32], (unsigned)cnt);
            unsigned long long* dst = g_cand + (size_t)bc * CAP2;
            for (int r = r0; r < r1; r++) {
                float s = tile[r * NC + c] * ctr_s[r];
                if (s > T0) {
                    if (base < CAP2) {
                        unsigned n = (unsigned)(n0 + r);
                        dst[base] = ((unsigned long long)__float_as_uint(s) << 32)
                                    | (0xFFFFFFFFu - n);
                    }
                    base++;
                }
            }
        }
    }
}

// ---------------------------------------------------------------------------
// Shared bitonic sort (descending) over P (power of 2) u64 keys, 256 threads
// ---------------------------------------------------------------------------
__device__ __forceinline__ void bitonic_desc(unsigned long long* cand, int P, int tid) {
    for (int kk = 2; kk <= P; kk <<= 1) {
        for (int jj = kk >> 1; jj > 0; jj >>= 1) {
            for (int i = tid; i < P; i += 256) {
                int ixj = i ^ jj;
                if (ixj > i) {
                    unsigned long long a = cand[i], bb = cand[ixj];
                    bool sw = ((i & kk) == 0) ? (a < bb) : (a > bb);
                    if (sw) { cand[i] = bb; cand[ixj] = a; }
                }
            }
            __syncthreads();
        }
    }
}

// ---------------------------------------------------------------------------
// K1: per (b,c): top-128 fast path (output-equivalent when >=100 survive NMS),
//     exact top-256 fallback otherwise. Forced to 8 blocks/SM.
// ---------------------------------------------------------------------------
__global__ void __launch_bounds__(256, 8) k_nms(const float* __restrict__ regs,
                                                const float* __restrict__ clf,
                                                const float* __restrict__ ctr) {
    __shared__ unsigned hist[HB];
    __shared__ unsigned long long cand[1024];
    __shared__ float4 bb[256];
    __shared__ unsigned srow[256 * 8];     // fallback suppression rows
    __shared__ unsigned scol[512];         // fast-path suppression columns [w*128+j]
    __shared__ unsigned keepw[8], keepr[8], sh_wt[8];
    __shared__ unsigned sh_Ta, sh_Tb, sh_cnt, sh_tot, sh_kept;

    int bc = blockIdx.x;
    int b = bc / NC;
    int c = bc % NC;
    int tid = threadIdx.x;
    int lane = tid & 31;
    int wrp = tid >> 5;

    int M = (int)g_cnt[bc * 32];
    const unsigned long long* src = g_cand + (size_t)bc * CAP2;
    bool srcok = (M >= KC && M <= CAP2);

    for (int i = tid; i < HB; i += 256) hist[i] = 0;
    if (tid == 0) { sh_cnt = 0; sh_tot = 0; sh_kept = 0; }
    __syncthreads();
    if (tid == 0) g_cnt[bc * 32] = 0;      // self-reset for next graph replay

    // ---- histogram ----
    if (srcok) {
        for (int i = tid; i < M; i += 256)
            atomicAdd(&hist[(unsigned)(src[i] >> 48) - HOFF], 1u);
    } else {
        const float* cb_ = clf + (size_t)b * NN * NC + c;
        const float* tb = ctr + (size_t)b * NN;
        unsigned loc = 0;
        for (int n = tid; n < NN; n += 256) {
            float s = cb_[(size_t)n * NC] * tb[n];
            if (s > CONF) { atomicAdd(&hist[(__float_as_uint(s) >> 16) - HOFF], 1u); loc++; }
        }
        atomicAdd(&sh_tot, loc);
    }
    __syncthreads();
    int tot = srcok ? M : (int)sh_tot;

    // ---- suffix sums over 256 coarse bins (3 fine each): shfl + 1 barrier ----
    unsigned csum = hist[tid * 3] + hist[tid * 3 + 1] + hist[tid * 3 + 2];
    unsigned sfx = csum;
    #pragma unroll
    for (int off = 1; off < 32; off <<= 1) {
        unsigned t = __shfl_down_sync(0xFFFFFFFFu, sfx, off);
        if (lane + off < 32) sfx += t;
    }
    if (lane == 0) sh_wt[wrp] = sfx;
    __syncthreads();
    {
        unsigned hi = 0;
        #pragma unroll
        for (int w2 = 0; w2 < 8; w2++) if (w2 > wrp) hi += sh_wt[w2];
        unsigned St = sfx + hi;
        unsigned Sn = St - csum;
        int tgtA = tot < 128 ? tot : 128;
        int tgtB = tot < KC ? tot : KC;
        if (tgtA == 0) { if (tid == 0) { sh_Ta = HB; sh_Tb = HB; } }
        else {
            if (St >= (unsigned)tgtA && Sn < (unsigned)tgtA) {
                unsigned cum = Sn; int bin = tid * 3 + 2;
                for (; bin >= tid * 3; bin--) { cum += hist[bin]; if (cum >= (unsigned)tgtA) break; }
                sh_Ta = (unsigned)(bin < tid * 3 ? tid * 3 : bin);
            }
            if (St >= (unsigned)tgtB && Sn < (unsigned)tgtB) {
                unsigned cum = Sn; int bin = tid * 3 + 2;
                for (; bin >= tid * 3; bin--) { cum += hist[bin]; if (cum >= (unsigned)tgtB) break; }
                sh_Tb = (unsigned)(bin < tid * 3 ? tid * 3 : bin);
            }
        }
    }
    __syncthreads();

    float y1 = 0.f, x1 = 0.f, y2 = 0.f, x2 = 0.f, score = 0.f;
    bool need256 = !srcok;
    int rt = bc & 255;

    // =================== FAST PATH: top-128 ===================
    if (!need256) {
        unsigned Ta = sh_Ta;
        for (int i = tid; i < M; i += 256) {
            unsigned long long key = src[i];
            if ((unsigned)(key >> 48) - HOFF >= Ta) {
                unsigned p = atomicAdd(&sh_cnt, 1u);
                if (p < 256) cand[p] = key;
            }
        }
        __syncthreads();
        int C = (int)sh_cnt;
        if (C > 256) need256 = true;
        else {
            for (int i = C + tid; i < 256; i += 256) cand[i] = 0ULL;
            __syncthreads();

            // register bitonic sort of 256 (desc): shfl intra-warp, smem jj>=32
            unsigned long long v = cand[tid];
            #pragma unroll
            for (int kk = 2; kk <= 32; kk <<= 1) {
                #pragma unroll
                for (int jj = kk >> 1; jj > 0; jj >>= 1) {
                    unsigned long long pv = __shfl_xor_sync(0xFFFFFFFFu, v, jj);
                    bool keep_max = (((tid & jj) == 0) == ((tid & kk) == 0));
                    if (keep_max ? (pv > v) : (pv < v)) v = pv;
                }
            }
            #pragma unroll
            for (int kk = 64; kk <= 256; kk <<= 1) {
                for (int jj = kk >> 1; jj >= 32; jj >>= 1) {
                    __syncthreads();
                    cand[tid] = v;
                    __syncthreads();
                    unsigned long long pv = cand[tid ^ jj];
                    bool keep_max = (((tid & jj) == 0) == ((tid & kk) == 0));
                    if (keep_max ? (pv > v) : (pv < v)) v = pv;
                }
                #pragma unroll
                for (int jj = 16; jj > 0; jj >>= 1) {
                    unsigned long long pv = __shfl_xor_sync(0xFFFFFFFFu, v, jj);
                    bool keep_max = (((tid & jj) == 0) == ((tid & kk) == 0));
                    if (keep_max ? (pv > v) : (pv < v)) v = pv;
                }
            }

            unsigned long long key = v;
            unsigned bits = (unsigned)(key >> 32);
            score = __uint_as_float(bits);
            unsigned n = 0xFFFFFFFFu - (unsigned)(key & 0xFFFFFFFFu);
            bool validk = (key != 0ULL);
            y1 = x1 = y2 = x2 = 0.f;
            if (validk) {
                int l, base;
                if (n < 16384u)      { l = 0; base = 0; }
                else if (n < 20480u) { l = 1; base = 16384; }
                else if (n < 21504u) { l = 2; base = 20480; }
                else if (n < 21760u) { l = 3; base = 21504; }
                else                 { l = 4; base = 21760; }
                int local = (int)n - base;
                int shift = 7 - l;
                float gx = (float)(local >> shift);
                float gy = (float)(local & ((1 << shift) - 1));
                float sF = (float)(8 << l);
                const float4 r = *reinterpret_cast<const float4*>(regs + ((size_t)b * NN + n) * 4);
                y1 = (gy - r.z) * sF; x1 = (gx - r.x) * sF;
                y2 = (gy + r.w) * sF; x2 = (gx + r.y) * sF;
            }
            if (!validk) score = 0.f;
            bb[tid] = make_float4(y1, x1, y2, x2);
            int keepf = (validk && score > CONF) ? 1 : 0;
            unsigned bal0 = __ballot_sync(0xFFFFFFFFu, keepf);
            if (lane == 0) keepw[wrp] = bal0;
            __syncthreads();

            // column-major suppression (ballot-free), SMSP-balanced:
            // warps 0-3: (cbk=w, lo half rows); warps 4-7: (cbk=7-w, hi half).
            // SMSP s gets loads (16s+15) + (16(3-s)+15+..) ~ equal across s.
            {
                int half = wrp >> 2;
                int cbk = half ? (7 - wrp) : wrp;
                int jcol = cbk * 32 + lane;
                float4 cbox = bb[jcol];
                float ca = (cbox.z - cbox.x) * (cbox.w - cbox.y);
                int i0 = half ? (jcol >> 1) : 0;
                int i1 = half ? jcol : (jcol >> 1);
                unsigned cw0 = 0, cw1 = 0, cw2 = 0, cw3 = 0;
                #pragma unroll
                for (int w = 0; w < 4; w++) {
                    int s0 = i0 > w * 32 ? i0 : w * 32;
                    int e0 = i1 < w * 32 + 32 ? i1 : w * 32 + 32;
                    unsigned acc = 0;
                    for (int i = s0; i < e0; i++) {
                        float4 o = bb[i];
                        float ai = (o.z - o.x) * (o.w - o.y);
                        float ih = fminf(o.z, cbox.z) - fmaxf(o.x, cbox.x); ih = fmaxf(ih, 0.0f);
                        float iw = fminf(o.w, cbox.w) - fmaxf(o.y, cbox.y); iw = fmaxf(iw, 0.0f);
                        float inter = ih * iw;
                        float uni = ai + ca - inter; uni = fmaxf(uni, 1e-8f);
                        if (inter > 0.5f * uni) acc |= 1u << (i - w * 32);
                    }
                    if (w == 0) cw0 = acc; else if (w == 1) cw1 = acc;
                    else if (w == 2) cw2 = acc; else cw3 = acc;
                }
                if (!half) {
                    scol[jcol] = cw0; scol[128 + jcol] = cw1;
                    scol[256 + jcol] = cw2; scol[384 + jcol] = cw3;
                }
                __syncthreads();
                if (half) {
                    scol[jcol] |= cw0; scol[128 + jcol] |= cw1;
                    scol[256 + jcol] |= cw2; scol[384 + jcol] |= cw3;
                }
            }
            __syncthreads();

            if (tid == rt) {
                unsigned k0 = keepw[0], k1 = keepw[1], k2 = keepw[2], k3 = keepw[3];
                #pragma unroll 4
                for (int j = 0; j < 128; j++) {
                    unsigned sup = (scol[j] & k0) | (scol[128 + j] & k1)
                                 | (scol[256 + j] & k2) | (scol[384 + j] & k3);
                    if (sup) {
                        unsigned m = ~(1u << (j & 31));
                        if (j < 32) k0 &= m; else if (j < 64) k1 &= m;
                        else if (j < 96) k2 &= m; else k3 &= m;
                    }
                }
                keepr[0] = k0; keepr[1] = k1; keepr[2] = k2; keepr[3] = k3;
                keepr[4] = 0; keepr[5] = 0; keepr[6] = 0; keepr[7] = 0;
                sh_kept = (unsigned)(__popc(k0) + __popc(k1) + __popc(k2) + __popc(k3));
            }
            __syncthreads();
            if ((int)sh_kept < MPC) need256 = true;
        }
    }

    // =================== FALLBACK: exact top-256 ===================
    if (need256) {
        for (int i = tid; i < 2048; i += 256) srow[i] = 0;
        if (tid == 0) sh_cnt = 0;
        __syncthreads();
        unsigned Tb = sh_Tb;
        if (srcok) {
            for (int i = tid; i < M; i += 256) {
                unsigned long long key = src[i];
                if ((unsigned)(key >> 48) - HOFF >= Tb) {
                    unsigned p = atomicAdd(&sh_cnt, 1u);
                    if (p < 1024) cand[p] = key;
                }
            }
        } else {
            const float* cb_ = clf + (size_t)b * NN * NC + c;
            const float* tb = ctr + (size_t)b * NN;
            for (int n = tid; n < NN; n += 256) {
                float s = cb_[(size_t)n * NC] * tb[n];
                if (s > CONF) {
                    unsigned bits = __float_as_uint(s);
                    if ((bits >> 16) - HOFF >= Tb) {
                        unsigned p = atomicAdd(&sh_cnt, 1u);
                        if (p < 1024) cand[p] = ((unsigned long long)bits << 32)
                                                | (0xFFFFFFFFu - (unsigned)n);
                    }
                }
            }
        }
        __syncthreads();
        int C = (int)sh_cnt; if (C > 1024) C = 1024;
        int P = (C <= 512) ? 512 : 1024;
        for (int i = C + tid; i < P; i += 256) cand[i] = 0ULL;
        __syncthreads();
        bitonic_desc(cand, P, tid);

        unsigned long long key = cand[tid];
        unsigned bits = (unsigned)(key >> 32);
        score = __uint_as_float(bits);
        unsigned n = 0xFFFFFFFFu - (unsigned)(key & 0xFFFFFFFFu);
        bool validk = (key != 0ULL);
        y1 = x1 = y2 = x2 = 0.f;
        if (validk) {
            int l, base;
            if (n < 16384u)      { l = 0; base = 0; }
            else if (n < 20480u) { l = 1; base = 16384; }
            else if (n < 21504u) { l = 2; base = 20480; }
            else if (n < 21760u) { l = 3; base = 21504; }
            else                 { l = 4; base = 21760; }
            int local = (int)n - base;
            int shift = 7 - l;
            float gx = (float)(local >> shift);
            float gy = (float)(local & ((1 << shift) - 1));
            float sF = (float)(8 << l);
            const float4 r = *reinterpret_cast<const float4*>(regs + ((size_t)b * NN + n) * 4);
            y1 = (gy - r.z) * sF; x1 = (gx - r.x) * sF;
            y2 = (gy + r.w) * sF; x2 = (gx + r.y) * sF;
        }
        if (!validk) score = 0.f;
        bb[tid] = make_float4(y1, x1, y2, x2);
        float aj = (y2 - y1) * (x2 - x1);
        int keepf = (validk && score > CONF) ? 1 : 0;
        unsigned bal0 = __ballot_sync(0xFFFFFFFFu, keepf);
        if (lane == 0) keepw[wrp] = bal0;
        __syncthreads();

        // full triangle IoU: warp w computes word w for rows < 32w+31
        {
            int lim = 32 * wrp + 31;
            for (int i = 0; i < lim; i++) {
                float4 o = bb[i];
                float ai = (o.z - o.x) * (o.w - o.y);
                float ih = fminf(o.z, y2) - fmaxf(o.x, y1); ih = fmaxf(ih, 0.0f);
                float iw = fminf(o.w, x2) - fmaxf(o.y, x1); iw = fmaxf(iw, 0.0f);
                float inter = ih * iw;
                float uni = ai + aj - inter; uni = fmaxf(uni, 1e-8f);
                bool pred = (tid > i) && (inter > 0.5f * uni);
                unsigned bl = __ballot_sync(0xFFFFFFFFu, pred);
                if ((tid & 31) == 0) srow[i * 8 + wrp] = bl;
            }
        }
        __syncthreads();

        if (tid == rt) {
            unsigned kw[8];
            #pragma unroll
            for (int w = 0; w < 8; w++) kw[w] = keepw[w];
            #pragma unroll 4
            for (int i = 0; i < 256; i++) {
                if ((kw[i >> 5] >> (i & 31)) & 1u) {
                    const uint4 s0 = *reinterpret_cast<const uint4*>(&srow[i * 8]);
                    const uint4 s1 = *reinterpret_cast<const uint4*>(&srow[i * 8 + 4]);
                    kw[0] &= ~s0.x; kw[1] &= ~s0.y; kw[2] &= ~s0.z; kw[3] &= ~s0.w;
                    kw[4] &= ~s1.x; kw[5] &= ~s1.y; kw[6] &= ~s1.z; kw[7] &= ~s1.w;
                }
            }
            #pragma unroll
            for (int w = 0; w < 8; w++) keepr[w] = kw[w];
        }
        __syncthreads();
    }

    // ---- stable partition via ballot scan (1 barrier) ----
    int keep_j = (keepr[wrp] >> lane) & 1;
    unsigned balk = __ballot_sync(0xFFFFFFFFu, keep_j);
    unsigned pre = __popc(balk & (0xFFFFFFFFu >> (31 - lane)));
    if (lane == 0) sh_wt[wrp] = __popc(balk);
    __syncthreads();
    unsigned base2 = 0, KT = 0;
    #pragma unroll
    for (int w2 = 0; w2 < 8; w2++) {
        unsigned t = sh_wt[w2];
        KT += t;
        if (w2 < wrp) base2 += t;
    }
    int incl = (int)(base2 + pre);
    int slot = keep_j ? (incl - 1) : ((int)KT + tid - incl);
    if (slot < MPC) {
        size_t o = (size_t)bc * MPC + slot;
        g_cls_scores[o] = keep_j ? score : 0.0f;
        float* ob = g_cls_boxes + o * 4;
        ob[0] = y1; ob[1] = x1; ob[2] = y2; ob[3] = x2;
    }
}

// ---------------------------------------------------------------------------
// K2: per batch final top-100 of 8000 (tie-break: lowest flat index)
// ---------------------------------------------------------------------------
__global__ __launch_bounds__(256) void k_final(float* __restrict__ out) {
    __shared__ unsigned hist[HB];
    __shared__ unsigned long long cand[2048];
    __shared__ unsigned f_wt[8];
    __shared__ unsigned sh_T, sh_cnt, sh_mode;

    int b = blockIdx.x, tid = threadIdx.x;
    int lane = tid & 31, wrp = tid >> 5;
    const int F = NC * MPC;  // 8000
    const float* s = g_cls_scores + (size_t)b * F;

    for (int i = tid; i < HB; i += 256) hist[i] = 0;
    if (tid == 0) sh_cnt = 0;
    __syncthreads();
    for (int f = tid; f < F; f += 256) {
        unsigned bits = __float_as_uint(s[f]);
        if (bits) atomicAdd(&hist[(bits >> 16) - HOFF], 1u);
    }
    __syncthreads();

    // parallel suffix scan over 256 coarse bins (3 fine each)
    unsigned csum = hist[tid * 3] + hist[tid * 3 + 1] + hist[tid * 3 + 2];
    unsigned sfx = csum;
    #pragma unroll
    for (int off = 1; off < 32; off <<= 1) {
        unsigned t = __shfl_down_sync(0xFFFFFFFFu, sfx, off);
        if (lane + off < 32) sfx += t;
    }
    if (lane == 0) f_wt[wrp] = sfx;
    __syncthreads();
    {
        unsigned hi = 0, tot = 0;
        #pragma unroll
        for (int w2 = 0; w2 < 8; w2++) {
            unsigned t = f_wt[w2];
            tot += t;
            if (w2 > wrp) hi += t;
        }
        unsigned St = sfx + hi, Sn = St - csum;
        if (tot >= MD) {
            if (St >= (unsigned)MD && Sn < (unsigned)MD) {
                unsigned cum = Sn; int bin = tid * 3 + 2;
                for (; bin >= tid * 3; bin--) { cum += hist[bin]; if (cum >= (unsigned)MD) break; }
                sh_T = (unsigned)(bin < tid * 3 ? tid * 3 : bin);
                sh_mode = 0;
            }
        } else if (tid == 0) { sh_T = 0; sh_mode = 1; }
    }
    __syncthreads();
    unsigned T = sh_T; int mode = (int)sh_mode;

    for (int f = tid; f < F; f += 256) {
        unsigned bits = __float_as_uint(s[f]);
        if (!bits) continue;
        unsigned k = (bits >> 16) - HOFF;
        if (mode == 1 || k >= T) {
            unsigned p = atomicAdd(&sh_cnt, 1u);
            if (p < 2048) cand[p] = ((unsigned long long)bits << 32) | (unsigned)(0xFFFFFFFFu - (unsigned)f);
        }
    }
    __syncthreads();
    int M = (int)sh_cnt; if (M > 2048) M = 2048;
    int P = 256; while (P < M) P <<= 1;
    for (int i = M + tid; i < P; i += 256) cand[i] = 0ULL;
    __syncthreads();

    bitonic_desc(cand, P, tid);

    float* outB = out;                       // [NB][MD][4]
    float* outL = out + (size_t)NB * MD * 4; // [NB][MD]
    float* outS = out + (size_t)NB * MD * 5; // [NB][MD]

    int lim = (mode == 0) ? MD : (M < MD ? M : MD);
    if (tid < lim) {
        unsigned long long key = cand[tid];
        unsigned bits = (unsigned)(key >> 32);
        float sv = __uint_as_float(bits);
        unsigned f = 0xFFFFFFFFu - (unsigned)(key & 0xFFFFFFFFu);
        int cls = (int)(f / MPC);
        float mul = (sv > 0.0f) ? 1.0f : 0.0f;
        const float* bx = g_cls_boxes + ((size_t)b * F + f) * 4;
        float* ob = outB + ((size_t)b * MD + tid) * 4;
        ob[0] = bx[0] * mul; ob[1] = bx[1] * mul; ob[2] = bx[2] * mul; ob[3] = bx[3] * mul;
        outL[b * MD + tid] = (float)cls;
        outS[b * MD + tid] = sv;
    }
    if (mode == 1 && tid == 0) {
        int slot = lim;
        for (int f = 0; f < F && slot < MD; f++) {
            if (__float_as_uint(s[f]) == 0u) {
                float* ob = outB + ((size_t)b * MD + slot) * 4;
                ob[0] = ob[1] = ob[2] = ob[3] = 0.0f;
                outL[b * MD + slot] = (float)(f / MPC);
                outS[b * MD + slot] = 0.0f;
                slot++;
            }
        }
    }
}

// ---------------------------------------------------------------------------
extern "C" void kernel_launch(void* const* d_in, const int* in_sizes, int n_in,
                              void* d_out, int out_size) {
    const float* regs = nullptr;
    const float* ctrs = nullptr;
    const float* clfs = nullptr;
    for (int i = 0; i < n_in; i++) {
        if (in_sizes[i] == NB * NN * 4)        regs = (const float*)d_in[i];
        else if (in_sizes[i] == NB * NN)       ctrs = (const float*)d_in[i];
        else if (in_sizes[i] == NB * NN * NC)  clfs = (const float*)d_in[i];
    }
    float* out = (float*)d_out;

    dim3 fgrid((NN + RPB - 1) / RPB, NB);    // 228 x 16
    k_filter<<<fgrid, 256>>>(clfs, ctrs);
    k_nms<<<NB * NC, 256>>>(regs, clfs, ctrs);
    k_final<<<NB, 256>>>(out);
}